// round 8
// baseline (speedup 1.0000x reference)
#include <cuda_runtime.h>
#include <cstdint>

// Patcher: x (8,3,1024,1024) fp32, patch=24, stride=16, reflect pad m=4.
// out[((b*64+ph)*64+pw)*1728 + (i*24+j)*3 + c] = x[b,c,ry,rx]
//   ry=reflect(ph*16+i-4), rx=reflect(pw*16+j-4); reflect: q<0->-q, q>1023->2046-q.
//
// Block (512 thr) = (b, ph, pg): 8 consecutive patches (pw = 8*pg..8*pg+7).
// smem tile s[r][x][c], c-fastest (= output order).
//   Phase 1: 3x LDG.128 (channel planes) -> in-lane transpose -> 3x STS.128.
//   Phase 2: LDS.128 + STG.128.cs (streaming: output is write-once, keep L2
//            for the reused input).
// 4 CTAs/SM x 16 warps = 64 warps = full occupancy; 39.2 KB smem.

static constexpr unsigned HWu = 1024u * 1024u;
static constexpr long long TOTAL_ELEMS = 56623104LL;
static constexpr unsigned ROW_F4 = 102u;              // 136*3/4 float4 per smem row
static constexpr unsigned SMEM_F4 = 24u * ROW_F4;     // 2448 float4 = 39168 B
static constexpr unsigned N_GROUPS = 24u * 34u;       // (r, xg) groups = 816
static constexpr unsigned N_OUT4 = 8u * 432u;         // 3456 float4 per block

__device__ __forceinline__ int reflect_idx(int q) {
    q = (q < 0) ? -q : q;
    q = (q > 1023) ? (2046 - q) : q;
    return q;
}

__device__ __forceinline__ void stcs4(float4* p, float4 v) {
    asm volatile("st.global.cs.v4.f32 [%0], {%1,%2,%3,%4};"
                 :: "l"(p), "f"(v.x), "f"(v.y), "f"(v.z), "f"(v.w)
                 : "memory");
}

__global__ void __launch_bounds__(512, 4)
patcher_kernel(const float* __restrict__ x, float* __restrict__ out,
               unsigned out_size) {
    __shared__ float4 s4[SMEM_F4];

    unsigned bid = blockIdx.x;
    unsigned tid = threadIdx.x;
    unsigned pg = bid & 7u;          // 8 groups of 8 patches
    unsigned ph = (bid >> 3) & 63u;
    unsigned b  = bid >> 9;

    if (bid == 0 && tid < 32u) {     // tail fill: flattened (nH,nW)=(64,64)
        unsigned idx = (unsigned)TOTAL_ELEMS + tid;
        if (idx < out_size) out[idx] = 64.0f;
    }

    // ---- Phase 1: stage + in-lane transpose ----
    const float* xb = x + (size_t)b * (3u * HWu);
    int ybase = (int)(ph << 4) - 4;
    int gx0   = (int)(pg << 7) - 4;   // tile x origin (pg*128 - 4)

    #pragma unroll
    for (unsigned it = 0; it < 2; ++it) {
        unsigned idx = tid + it * 512u;
        if (idx < N_GROUPS) {
            unsigned r  = idx / 34u;
            unsigned xg = idx - r * 34u;
            int y  = reflect_idx(ybase + (int)r);
            int gx = gx0 + (int)(xg << 2);

            const float* p = xb + (unsigned)y * 1024u;
            float4 a0, a1, a2;
            if (gx >= 0 && gx <= 1020) {
                a0 = *reinterpret_cast<const float4*>(p + gx);
                a1 = *reinterpret_cast<const float4*>(p + HWu + gx);
                a2 = *reinterpret_cast<const float4*>(p + 2u * HWu + gx);
            } else {
                int x0 = reflect_idx(gx), x1 = reflect_idx(gx + 1);
                int x2 = reflect_idx(gx + 2), x3 = reflect_idx(gx + 3);
                a0.x = p[x0]; a0.y = p[x1]; a0.z = p[x2]; a0.w = p[x3];
                const float* q1 = p + HWu;
                a1.x = q1[x0]; a1.y = q1[x1]; a1.z = q1[x2]; a1.w = q1[x3];
                const float* q2 = p + 2u * HWu;
                a2.x = q2[x0]; a2.y = q2[x1]; a2.z = q2[x2]; a2.w = q2[x3];
            }
            // transpose to c-fastest
            unsigned sbase = r * ROW_F4 + xg * 3u;
            float4 t0, t1, t2;
            t0.x = a0.x; t0.y = a1.x; t0.z = a2.x; t0.w = a0.y;
            t1.x = a1.y; t1.y = a2.y; t1.z = a0.z; t1.w = a1.z;
            t2.x = a2.z; t2.y = a0.w; t2.z = a1.w; t2.w = a2.w;
            s4[sbase + 0] = t0;
            s4[sbase + 1] = t1;
            s4[sbase + 2] = t2;
        }
    }
    __syncthreads();

    // ---- Phase 2: coalesced streaming copy out ----
    unsigned patch0 = (b << 12) + (ph << 6) + (pg << 3);
    float4* o4 = reinterpret_cast<float4*>(out) + (size_t)patch0 * 432u;

    // Incremental decode of idx -> (pl, i, off); idx steps by 512 per iter.
    unsigned idx = tid;
    unsigned pl  = idx / 432u;
    unsigned rem = idx - pl * 432u;
    unsigned i   = rem / 18u;
    unsigned off = rem - i * 18u;

    #pragma unroll
    for (unsigned it = 0; it < 7; ++it) {
        if (idx < N_OUT4) {
            stcs4(o4 + idx, s4[i * ROW_F4 + pl * 12u + off]);
        }
        // advance by 512 = 1 patch (432) + 80 = 4 rows (72) + 8 f4
        idx += 512u;
        pl  += 1u;
        i   += 4u;
        off += 8u;
        if (off >= 18u) { off -= 18u; i += 1u; }
        if (i >= 24u)   { i -= 24u; pl += 1u; }
        // pl can exceed 7 only when idx >= N_OUT4 (guarded above)
    }
}

extern "C" void kernel_launch(void* const* d_in, const int* in_sizes, int n_in,
                              void* d_out, int out_size) {
    const float* x = (const float*)d_in[0];
    float* out = (float*)d_out;
    patcher_kernel<<<4096, 512>>>(x, out, (unsigned)out_size);
}